// round 8
// baseline (speedup 1.0000x reference)
#include <cuda_runtime.h>
#include <cuda_bf16.h>
#include <cstdint>

#define HDIM 128
#define MH 64
#define MAXB 2048
#define ROWS_PER_BLOCK 1024
#define ROWS_PER_WARP 128
#define LN_EPS 1e-5f

// ---------------- scratch (static device globals; zero-initialized) -------
// ZERO is the identity for every array:
//   g_sum/g_sq/g_cnt : additive identity
//   g_maxb           : max of fkey(v);  fkey(finite) >= 0x00800000 > 0
//   g_minb           : max of fkey(-v) (min via negation); same bound
// mlp_kernel zeroes its graphs' slices after producing output, so every
// graph replay sees identity state without a separate init kernel.
__device__ float    g_sum [MAXB * HDIM];
__device__ float    g_sq  [MAXB * HDIM];
__device__ unsigned g_minb[MAXB * HDIM];   // max of fkey(-v)
__device__ unsigned g_maxb[MAXB * HDIM];   // max of fkey(v)
__device__ float    g_cnt [MAXB];

// order-preserving float <-> uint key (for atomicMax)
__device__ __forceinline__ unsigned fkey(float f) {
    unsigned b = __float_as_uint(f);
    return (b & 0x80000000u) ? ~b : (b | 0x80000000u);
}
__device__ __forceinline__ float funkey(unsigned k) {
    return __uint_as_float((k & 0x80000000u) ? (k ^ 0x80000000u) : ~k);
}

// ---------------- phase 1: segment reduction, warp-per-row float4 ----------
struct Acc4 {
    float4 s, q, mn, mx;
    int cnt;
};

__device__ __forceinline__ void acc_reset(Acc4& a, const float4& v) {
    a.s = v;
    a.q = make_float4(v.x * v.x, v.y * v.y, v.z * v.z, v.w * v.w);
    a.mn = v;
    a.mx = v;
    a.cnt = 1;
}
__device__ __forceinline__ void acc_add(Acc4& a, const float4& v) {
    a.s.x += v.x; a.s.y += v.y; a.s.z += v.z; a.s.w += v.w;
    a.q.x = fmaf(v.x, v.x, a.q.x);
    a.q.y = fmaf(v.y, v.y, a.q.y);
    a.q.z = fmaf(v.z, v.z, a.q.z);
    a.q.w = fmaf(v.w, v.w, a.q.w);
    a.mn.x = fminf(a.mn.x, v.x); a.mn.y = fminf(a.mn.y, v.y);
    a.mn.z = fminf(a.mn.z, v.z); a.mn.w = fminf(a.mn.w, v.w);
    a.mx.x = fmaxf(a.mx.x, v.x); a.mx.y = fmaxf(a.mx.y, v.y);
    a.mx.z = fmaxf(a.mx.z, v.z); a.mx.w = fmaxf(a.mx.w, v.w);
}

__device__ __forceinline__ void acc_flush(const Acc4& a, int seg, int colbase, int lane) {
    int o = seg * HDIM + colbase;
    atomicAdd(&g_sum[o + 0], a.s.x);
    atomicAdd(&g_sum[o + 1], a.s.y);
    atomicAdd(&g_sum[o + 2], a.s.z);
    atomicAdd(&g_sum[o + 3], a.s.w);
    atomicAdd(&g_sq[o + 0], a.q.x);
    atomicAdd(&g_sq[o + 1], a.q.y);
    atomicAdd(&g_sq[o + 2], a.q.z);
    atomicAdd(&g_sq[o + 3], a.q.w);
    atomicMax(&g_minb[o + 0], fkey(-a.mn.x));
    atomicMax(&g_minb[o + 1], fkey(-a.mn.y));
    atomicMax(&g_minb[o + 2], fkey(-a.mn.z));
    atomicMax(&g_minb[o + 3], fkey(-a.mn.w));
    atomicMax(&g_maxb[o + 0], fkey(a.mx.x));
    atomicMax(&g_maxb[o + 1], fkey(a.mx.y));
    atomicMax(&g_maxb[o + 2], fkey(a.mx.z));
    atomicMax(&g_maxb[o + 3], fkey(a.mx.w));
    if (lane == 0) atomicAdd(&g_cnt[seg], (float)a.cnt);
}

__global__ void __launch_bounds__(256) seg_phase1(const float4* __restrict__ x4,
                                                  const int* __restrict__ batch,
                                                  int N) {
    __shared__ int sb[ROWS_PER_BLOCK];
    const int tid = threadIdx.x;
    const int warp = tid >> 5;
    const int lane = tid & 31;
    const long long blockStart = (long long)blockIdx.x * ROWS_PER_BLOCK;
    const int rows = (int)min((long long)ROWS_PER_BLOCK, (long long)N - blockStart);
    if (rows <= 0) return;

    for (int i = tid; i < rows; i += 256) sb[i] = batch[blockStart + i];
    __syncthreads();

    const int wstart = warp * ROWS_PER_WARP;
    if (wstart >= rows) return;
    const int wend = min(wstart + ROWS_PER_WARP, rows);

    const float4* xp = x4 + (blockStart + wstart) * (HDIM / 4) + lane;

    Acc4 a;
    int cur = sb[wstart];
    {
        float4 v0 = __ldcs(xp);
        acc_reset(a, v0);
        xp += HDIM / 4;
    }

    int i = wstart + 1;
    for (; i + 8 <= wend; i += 8) {
        float4 v[8];
#pragma unroll
        for (int j = 0; j < 8; ++j) v[j] = __ldcs(xp + j * (HDIM / 4));
        if (sb[i + 7] == cur) {
#pragma unroll
            for (int j = 0; j < 8; ++j) acc_add(a, v[j]);
            a.cnt += 8;
        } else {
#pragma unroll
            for (int j = 0; j < 8; ++j) {
                int sg = sb[i + j];
                if (sg != cur) {
                    acc_flush(a, cur, lane * 4, lane);
                    cur = sg;
                    acc_reset(a, v[j]);
                } else {
                    acc_add(a, v[j]);
                    a.cnt++;
                }
            }
        }
        xp += 8 * (HDIM / 4);
    }
    for (; i < wend; ++i) {
        float4 v = __ldcs(xp);
        int sg = sb[i];
        if (sg != cur) {
            acc_flush(a, cur, lane * 4, lane);
            cur = sg;
            acc_reset(a, v);
        } else {
            acc_add(a, v);
            a.cnt++;
        }
        xp += HDIM / 4;
    }
    acc_flush(a, cur, lane * 4, lane);
}

// ------- phase 2: 2 graphs/block, weights amortized, 256 threads -----------
__global__ void __launch_bounds__(256) mlp_kernel(
    const float* __restrict__ u,
    const float* __restrict__ W0, const float* __restrict__ b0,
    const float* __restrict__ W1, const float* __restrict__ b1,
    const float* __restrict__ W2, const float* __restrict__ b2,
    const float* __restrict__ lng, const float* __restrict__ lnb,
    const float* __restrict__ W3, const float* __restrict__ b3,
    float* __restrict__ out, int B) {
    const int t = threadIdx.x;
    const int gb = blockIdx.x * 2;
    // duplicate slot 1 onto the last graph when B is odd (writes are identical)
    const int g0 = gb;
    const int g1 = (gb + 1 < B) ? gb + 1 : gb;

    __shared__ float concat[2][5 * HDIM];     // 5 KB
    __shared__ float part0[16][2][MH];        // 8 KB
    __shared__ float part1[4][2][MH];         // 2 KB
    __shared__ float part3[2][2][HDIM];       // 2 KB
    __shared__ float h0[2][MH];
    __shared__ float hb[2][MH];

    // ---- build concat = [u, s, min, max, var] for both graphs ----
    for (int idx = t; idx < 2 * 5 * HDIM; idx += 256) {
        int g = idx / (5 * HDIM);
        int j = idx - g * (5 * HDIM);
        int gid = g ? g1 : g0;
        int o = gid * HDIM + (j & (HDIM - 1));
        int sec = j >> 7;
        float val;
        if (sec == 0) {
            val = u[o];
        } else if (sec == 1) {
            val = g_sum[o];
        } else if (sec == 2) {
            val = -funkey(g_minb[o]);
        } else if (sec == 3) {
            val = funkey(g_maxb[o]);
        } else {
            float cv = fmaxf(g_cnt[gid], 1.0f);
            float me = g_sum[o] / cv;
            val = g_sq[o] / cv - me * me;
        }
        concat[g][j] = val;
    }
    __syncthreads();

    // ---- layer 0: 640 -> 64; 16-way K-split, 4 outputs x 2 graphs/thread ----
    {
        const int mg = (t & 15) * 4;
        const int q  = t >> 4;             // 0..15
        float a00 = 0.f, a01 = 0.f, a02 = 0.f, a03 = 0.f;
        float a10 = 0.f, a11 = 0.f, a12 = 0.f, a13 = 0.f;
        const int k0 = q * 40;
#pragma unroll 8
        for (int k = k0; k < k0 + 40; ++k) {
            float4 w = *(const float4*)&W0[k * MH + mg];
            float c0 = concat[0][k];
            float c1 = concat[1][k];
            a00 = fmaf(c0, w.x, a00); a01 = fmaf(c0, w.y, a01);
            a02 = fmaf(c0, w.z, a02); a03 = fmaf(c0, w.w, a03);
            a10 = fmaf(c1, w.x, a10); a11 = fmaf(c1, w.y, a11);
            a12 = fmaf(c1, w.z, a12); a13 = fmaf(c1, w.w, a13);
        }
        part0[q][0][mg + 0] = a00; part0[q][0][mg + 1] = a01;
        part0[q][0][mg + 2] = a02; part0[q][0][mg + 3] = a03;
        part0[q][1][mg + 0] = a10; part0[q][1][mg + 1] = a11;
        part0[q][1][mg + 2] = a12; part0[q][1][mg + 3] = a13;
    }
    __syncthreads();
    if (t < 2 * MH) {
        int g = t >> 6, m = t & 63;
        float s = 0.f;
#pragma unroll
        for (int q = 0; q < 16; ++q) s += part0[q][g][m];
        h0[g][m] = fmaxf(s + b0[m], 0.f);
    }
    __syncthreads();

    // ---- layer 1: 64 -> 64; 4-way K-split x 2 graphs ----
    {
        const int m = t & 63;
        const int q = t >> 6;
        float ac0 = 0.f, ac1 = 0.f;
        const int k0 = q * 16;
#pragma unroll
        for (int k = k0; k < k0 + 16; ++k) {
            float w = __ldg(&W1[k * MH + m]);
            ac0 = fmaf(h0[0][k], w, ac0);
            ac1 = fmaf(h0[1][k], w, ac1);
        }
        part1[q][0][m] = ac0;
        part1[q][1][m] = ac1;
    }
    __syncthreads();
    if (t < 2 * MH) {
        int g = t >> 6, m = t & 63;
        hb[g][m] = fmaxf(part1[0][g][m] + part1[1][g][m] + part1[2][g][m] +
                         part1[3][g][m] + b1[m], 0.f);
    }
    __syncthreads();

    // ---- layer 2: 64 -> 64; 4-way K-split x 2 graphs ----
    {
        const int m = t & 63;
        const int q = t >> 6;
        float ac0 = 0.f, ac1 = 0.f;
        const int k0 = q * 16;
#pragma unroll
        for (int k = k0; k < k0 + 16; ++k) {
            float w = __ldg(&W2[k * MH + m]);
            ac0 = fmaf(hb[0][k], w, ac0);
            ac1 = fmaf(hb[1][k], w, ac1);
        }
        part1[q][0][m] = ac0;
        part1[q][1][m] = ac1;
    }
    __syncthreads();
    if (t < 2 * MH) {
        int g = t >> 6, m = t & 63;
        h0[g][m] = fmaxf(part1[0][g][m] + part1[1][g][m] + part1[2][g][m] +
                         part1[3][g][m] + b2[m], 0.f);
    }
    __syncthreads();

    // ---- layernorm: warp g handles graph g (shuffle reduce over 64) ----
    if (t < 64) {
        const int g = t >> 5;
        const int lane = t & 31;
        float v0 = h0[g][lane], v1 = h0[g][lane + 32];
        float s = v0 + v1;
#pragma unroll
        for (int o = 16; o > 0; o >>= 1) s += __shfl_xor_sync(0xFFFFFFFF, s, o);
        float mu = s * (1.0f / MH);
        float d0 = v0 - mu, d1 = v1 - mu;
        float vs = d0 * d0 + d1 * d1;
#pragma unroll
        for (int o = 16; o > 0; o >>= 1) vs += __shfl_xor_sync(0xFFFFFFFF, vs, o);
        float rstd = rsqrtf(vs * (1.0f / MH) + LN_EPS);
        hb[g][lane]      = d0 * rstd * lng[lane]      + lnb[lane];
        hb[g][lane + 32] = d1 * rstd * lng[lane + 32] + lnb[lane + 32];
    }
    __syncthreads();

    // ---- output layer: 64 -> 128; 2-way K-split x 2 graphs ----
    {
        const int col = t & 127;
        const int hf  = t >> 7;
        float ac0 = 0.f, ac1 = 0.f;
        const int k0 = hf * 32;
#pragma unroll 8
        for (int k = k0; k < k0 + 32; ++k) {
            float w = __ldg(&W3[k * HDIM + col]);
            ac0 = fmaf(hb[0][k], w, ac0);
            ac1 = fmaf(hb[1][k], w, ac1);
        }
        part3[hf][0][col] = ac0;
        part3[hf][1][col] = ac1;
    }
    __syncthreads();
    {
        const int g = t >> 7;             // 0 or 1
        const int col = t & 127;
        const int gid = g ? g1 : g0;
        int o = gid * HDIM + col;
        out[o] = u[o] + b3[col] + part3[0][g][col] + part3[1][g][col];

        // reset scratch slice to zero-identity for next replay
        g_sum[o] = 0.f;
        g_sq[o] = 0.f;
        g_minb[o] = 0u;
        g_maxb[o] = 0u;
        if (col == 0) g_cnt[gid] = 0.f;
    }
}

// ---------------- launch ----------------
extern "C" void kernel_launch(void* const* d_in, const int* in_sizes, int n_in,
                              void* d_out, int out_size) {
    const float* x     = (const float*)d_in[0];
    // d_in[1] edge_index, d_in[2] edge_attr : unused by the forward
    const float* u     = (const float*)d_in[3];
    const int*   batch = (const int*)d_in[4];
    const float* W0    = (const float*)d_in[5];
    const float* b0    = (const float*)d_in[6];
    const float* W1    = (const float*)d_in[7];
    const float* b1    = (const float*)d_in[8];
    const float* W2    = (const float*)d_in[9];
    const float* b2    = (const float*)d_in[10];
    const float* lng   = (const float*)d_in[11];
    const float* lnb   = (const float*)d_in[12];
    const float* W3    = (const float*)d_in[13];
    const float* b3    = (const float*)d_in[14];
    float* out = (float*)d_out;

    const int N = in_sizes[0] / HDIM;
    int B = in_sizes[3] / HDIM;
    if (B > MAXB) B = MAXB;

    const int nBlocks = (N + ROWS_PER_BLOCK - 1) / ROWS_PER_BLOCK;
    seg_phase1<<<nBlocks, 256>>>((const float4*)x, batch, N);

    mlp_kernel<<<(B + 1) / 2, 256>>>(u, W0, b0, W1, b1, W2, b2,
                                     lng, lnb, W3, b3, out, B);
}